// round 15
// baseline (speedup 1.0000x reference)
#include <cuda_runtime.h>
#include <cuda_fp16.h>
#include <mma.h>
#include <cstdint>

using namespace nvcuda;

// Problem constants (fixed shapes per reference)
#define NN 100000
#define NE 1600000
#define DIN 128
#define DH 64
#define NB_SCAN ((NN + 1023) / 1024)   // 98

// ---------------- scratch (no allocations allowed) ----------------
__device__ float  g_dinv[NN];
__device__ int    g_cnt[NN];
__device__ int    g_rowptr[NN];
__device__ int    g_cursor[NN];
__device__ int    g_bsum[NB_SCAN];
__device__ int    g_csr_src[NE];
__device__ __half g_Xh [NN * DIN];     // X converted to fp16
__device__ __half g_W1h[DIN * DH];
__device__ __half g_W2h[DH * DH];
__device__ __half g_Xl_h [NN * DH];    // layer-1 transformed features (gather-1 source)
__device__ __half g_Xl2_h[NN * DH];    // layer-2 transformed features (gather-2 source)

// ---------------- CSR build ----------------
__global__ void k_zero_cnt(int n) {
    int i = blockIdx.x * blockDim.x + threadIdx.x;
    if (i < n) g_cnt[i] = 0;
}

__global__ void k_hist(const int* __restrict__ dst, int nE) {
    int e = blockIdx.x * blockDim.x + threadIdx.x;
    if (e < nE) atomicAdd(&g_cnt[dst[e]], 1);
}

__global__ __launch_bounds__(1024) void k_scan1(int n) {
    __shared__ int s[1024];
    int i = blockIdx.x * 1024 + threadIdx.x;
    int v = (i < n) ? g_cnt[i] : 0;
    s[threadIdx.x] = v;
    __syncthreads();
    for (int off = 1; off < 1024; off <<= 1) {
        int t = (threadIdx.x >= off) ? s[threadIdx.x - off] : 0;
        __syncthreads();
        s[threadIdx.x] += t;
        __syncthreads();
    }
    if (i < n) g_rowptr[i] = s[threadIdx.x] - v;       // exclusive (block-local)
    if (threadIdx.x == 1023) g_bsum[blockIdx.x] = s[1023];
}

// merged scan2+scan3: finalize rowptr, init cursor, compute dinv.
__global__ __launch_bounds__(256) void k_scan23(int n) {
    __shared__ int sP;
    const int q = blockIdx.x >> 2;
    if (threadIdx.x < 32) {
        int v = 0;
        for (int j = threadIdx.x; j < q; j += 32) v += g_bsum[j];
#pragma unroll
        for (int o = 16; o > 0; o >>= 1) v += __shfl_down_sync(0xffffffffu, v, o);
        if (threadIdx.x == 0) sP = v;
    }
    __syncthreads();
    int i = blockIdx.x * 256 + threadIdx.x;
    if (i >= n) return;
    int rp = g_rowptr[i] + sP;
    g_rowptr[i] = rp;
    g_cursor[i] = rp;
    g_dinv[i] = rsqrtf((float)g_cnt[i] + 1.0f);
}

__global__ void k_scatter(const int* __restrict__ src, const int* __restrict__ dst, int nE) {
    int e = blockIdx.x * blockDim.x + threadIdx.x;
    if (e >= nE) return;
    int d = dst[e];
    int pos = atomicAdd(&g_cursor[d], 1);
    g_csr_src[pos] = src[e];
}

// ---------------- conversions (X + W1 + W2, one kernel) ----------------
__global__ void k_conv(const float* __restrict__ X, const float* __restrict__ W1,
                       const float* __restrict__ W2, long nX4) {
    long i = (long)blockIdx.x * blockDim.x + threadIdx.x;
    if (i < nX4) {
        float4 v = reinterpret_cast<const float4*>(X)[i];
        __half2 h[2];
        h[0] = __floats2half2_rn(v.x, v.y);
        h[1] = __floats2half2_rn(v.z, v.w);
        reinterpret_cast<uint2*>(g_Xh)[i] = *reinterpret_cast<uint2*>(h);
    } else {
        long j = i - nX4;
        if (j < DIN * DH) g_W1h[j] = __float2half_rn(W1[j]);
        if (j < DH * DH)  g_W2h[j] = __float2half_rn(W2[j]);
    }
}

// ---------------- tensor-core GEMM: out = fp16( Xh @ Wh ), fp32 accum ----------------
template <int K>
__global__ __launch_bounds__(256) void k_gemm_tc(const __half* __restrict__ Xh,
                                                 const __half* __restrict__ Wh,
                                                 __half* __restrict__ outh, int n) {
    constexpr int KT = 64;
    constexpr int NT = K / KT;
    __shared__ __half sA[128][72];
    __shared__ __half sB[64][72];
    __shared__ float  sStage[8][16 * 20];

    const int tid = threadIdx.x;
    const int wid = tid >> 5;
    const int lane = tid & 31;
    const int node0 = blockIdx.x * 128;

    const int ar = tid >> 1;
    const int as = (tid & 1) * 32;
    const int br = tid >> 2;
    const int bs = (tid & 3) * 16;

    wmma::fragment<wmma::accumulator, 16, 16, 16, float> facc[4];
#pragma unroll
    for (int c = 0; c < 4; c++) wmma::fill_fragment(facc[c], 0.0f);

    for (int kt = 0; kt < NT; kt++) {
        {
            const int node = node0 + ar;
            if (node < n) {
                const uint4* srcp = reinterpret_cast<const uint4*>(
                    Xh + (size_t)node * K + kt * KT + as);
                uint4* dstp = reinterpret_cast<uint4*>(&sA[ar][as]);
#pragma unroll
                for (int u = 0; u < 4; u++) dstp[u] = srcp[u];
            } else {
                uint4 z = make_uint4(0, 0, 0, 0);
                uint4* dstp = reinterpret_cast<uint4*>(&sA[ar][as]);
#pragma unroll
                for (int u = 0; u < 4; u++) dstp[u] = z;
            }
        }
        {
            const uint4* srcp = reinterpret_cast<const uint4*>(
                Wh + (size_t)(kt * KT + br) * DH + bs);
            uint4* dstp = reinterpret_cast<uint4*>(&sB[br][bs]);
            dstp[0] = srcp[0];
            dstp[1] = srcp[1];
        }
        __syncthreads();

#pragma unroll
        for (int k8 = 0; k8 < KT / 16; k8++) {
            wmma::fragment<wmma::matrix_a, 16, 16, 16, __half, wmma::row_major> fa;
            wmma::load_matrix_sync(fa, &sA[wid * 16][k8 * 16], 72);
#pragma unroll
            for (int c = 0; c < 4; c++) {
                wmma::fragment<wmma::matrix_b, 16, 16, 16, __half, wmma::row_major> fb;
                wmma::load_matrix_sync(fb, &sB[k8 * 16][c * 16], 72);
                wmma::mma_sync(facc[c], fa, fb, facc[c]);
            }
        }
        if (kt + 1 < NT) __syncthreads();
    }

    const int erow = lane >> 1;
    const int eseg = (lane & 1) * 8;
#pragma unroll
    for (int c = 0; c < 4; c++) {
        wmma::store_matrix_sync(&sStage[wid][0], facc[c], 20, wmma::mem_row_major);
        __syncwarp();
        const int node = node0 + wid * 16 + erow;
        if (node < n) {
            const float* sp = &sStage[wid][erow * 20 + eseg];
            __half2 h[4];
            h[0] = __floats2half2_rn(sp[0], sp[1]);
            h[1] = __floats2half2_rn(sp[2], sp[3]);
            h[2] = __floats2half2_rn(sp[4], sp[5]);
            h[3] = __floats2half2_rn(sp[6], sp[7]);
            *reinterpret_cast<uint4*>(outh + (size_t)node * DH + c * 16 + eseg) =
                *reinterpret_cast<uint4*>(h);
        }
        __syncwarp();
    }
}

// ---------------- FUSED gather1 + layer-2 transform ----------------
// One warp per node; lane owns 2 columns (half2 per row load).
//   acc = dinv[gw]*Xl[gw] + sum dinv[s]*Xl[s]          (fp32)
//   H   = relu(acc*dinv + b1)                          (fp32, in regs)
//   Xl2[gw] = H @ W2  (64x64 matvec via shfl + smem W2), written fp16.
// Eliminates the separate GEMM2 kernel and the H buffer round-trip.
__global__ __launch_bounds__(256) void k_gather_fused(const float* __restrict__ bias) {
    __shared__ __half2 sW2[DH * 32];    // 8KB: W2 row-major as half2 pairs
    {
        // straight copy of g_W2h (64x64 halves = 2048 half2), 8 per thread
        const __half2* src = reinterpret_cast<const __half2*>(g_W2h);
#pragma unroll
        for (int u = 0; u < 8; u++)
            sW2[threadIdx.x + u * 256] = src[threadIdx.x + u * 256];
    }
    __syncthreads();

    int gw = (blockIdx.x * blockDim.x + threadIdx.x) >> 5;
    if (gw >= NN) return;
    const int lane = threadIdx.x & 31;
    const int start = g_rowptr[gw];
    const int cnt   = g_cnt[gw];
    const float dvd = g_dinv[gw];
    const __half2* base = reinterpret_cast<const __half2*>(g_Xl_h);

    float2 acc;
    {
        float2 sf = __half22float2(base[(size_t)gw * 32 + lane]);
        acc.x = sf.x * dvd;
        acc.y = sf.y * dvd;
    }

    int j0 = 0;
    for (; j0 + 32 <= cnt; j0 += 32) {
        int   myidx = g_csr_src[start + j0 + lane];
        float myd   = g_dinv[myidx];
#pragma unroll
        for (int t = 0; t < 32; t++) {
            int   s = __shfl_sync(0xffffffffu, myidx, t);
            float d = __shfl_sync(0xffffffffu, myd,   t);
            float2 v = __half22float2(base[(size_t)s * 32 + lane]);
            acc.x = fmaf(d, v.x, acc.x);
            acc.y = fmaf(d, v.y, acc.y);
        }
    }
    int rem = cnt - j0;
    if (rem > 0) {
        int   myidx = 0; float myd = 0.f;
        if (lane < rem) {
            myidx = g_csr_src[start + j0 + lane];
            myd   = g_dinv[myidx];
        }
        for (int t = 0; t < rem; t++) {
            int   s = __shfl_sync(0xffffffffu, myidx, t);
            float d = __shfl_sync(0xffffffffu, myd,   t);
            float2 v = __half22float2(base[(size_t)s * 32 + lane]);
            acc.x = fmaf(d, v.x, acc.x);
            acc.y = fmaf(d, v.y, acc.y);
        }
    }

    // H = relu(acc*dinv + b1), kept fp32 in regs
    float2 bb = *reinterpret_cast<const float2*>(bias + lane * 2);
    float2 hv;
    hv.x = fmaxf(fmaf(acc.x, dvd, bb.x), 0.f);
    hv.y = fmaxf(fmaf(acc.y, dvd, bb.y), 0.f);

    // Xl2[gw][2*lane .. 2*lane+1] = sum_k H[k] * W2[k][c]
    float2 o = make_float2(0.f, 0.f);
#pragma unroll
    for (int t = 0; t < 32; t++) {
        float hx = __shfl_sync(0xffffffffu, hv.x, t);   // H[2t]
        float hy = __shfl_sync(0xffffffffu, hv.y, t);   // H[2t+1]
        float2 w0 = __half22float2(sW2[(2 * t) * 32 + lane]);
        float2 w1 = __half22float2(sW2[(2 * t + 1) * 32 + lane]);
        o.x = fmaf(hx, w0.x, o.x);
        o.x = fmaf(hy, w1.x, o.x);
        o.y = fmaf(hx, w0.y, o.y);
        o.y = fmaf(hy, w1.y, o.y);
    }
    reinterpret_cast<__half2*>(g_Xl2_h)[(size_t)gw * 32 + lane] =
        __floats2half2_rn(o.x, o.y);
}

// ---------------- final gather (layer 2): out = dinv*(sum) + b2 ----------------
__global__ __launch_bounds__(256) void k_gather_out(const float* __restrict__ bias,
                                                    float* __restrict__ outbuf, int n) {
    int gw = (blockIdx.x * blockDim.x + threadIdx.x) >> 5;
    if (gw >= n) return;
    const int lane = threadIdx.x & 31;
    const int start = g_rowptr[gw];
    const int cnt   = g_cnt[gw];
    const float dvd = g_dinv[gw];
    const __half2* base = reinterpret_cast<const __half2*>(g_Xl2_h);

    float2 acc;
    {
        float2 sf = __half22float2(base[(size_t)gw * 32 + lane]);
        acc.x = sf.x * dvd;
        acc.y = sf.y * dvd;
    }

    int j0 = 0;
    for (; j0 + 32 <= cnt; j0 += 32) {
        int   myidx = g_csr_src[start + j0 + lane];
        float myd   = g_dinv[myidx];
#pragma unroll
        for (int t = 0; t < 32; t++) {
            int   s = __shfl_sync(0xffffffffu, myidx, t);
            float d = __shfl_sync(0xffffffffu, myd,   t);
            float2 v = __half22float2(base[(size_t)s * 32 + lane]);
            acc.x = fmaf(d, v.x, acc.x);
            acc.y = fmaf(d, v.y, acc.y);
        }
    }
    int rem = cnt - j0;
    if (rem > 0) {
        int   myidx = 0; float myd = 0.f;
        if (lane < rem) {
            myidx = g_csr_src[start + j0 + lane];
            myd   = g_dinv[myidx];
        }
        for (int t = 0; t < rem; t++) {
            int   s = __shfl_sync(0xffffffffu, myidx, t);
            float d = __shfl_sync(0xffffffffu, myd,   t);
            float2 v = __half22float2(base[(size_t)s * 32 + lane]);
            acc.x = fmaf(d, v.x, acc.x);
            acc.y = fmaf(d, v.y, acc.y);
        }
    }

    float2 bb = *reinterpret_cast<const float2*>(bias + lane * 2);
    float2 o;
    o.x = fmaf(acc.x, dvd, bb.x);
    o.y = fmaf(acc.y, dvd, bb.y);
    *reinterpret_cast<float2*>(outbuf + (size_t)gw * DH + lane * 2) = o;
}

// ---------------- host launch ----------------
extern "C" void kernel_launch(void* const* d_in, const int* in_sizes, int n_in,
                              void* d_out, int out_size) {
    const int*   E  = nullptr;
    const float* X  = nullptr;
    const float* W1 = nullptr;
    const float* b1 = nullptr;
    const float* W2 = nullptr;
    const float* b2 = nullptr;
    long nE_total = 0;
    for (int i = 0; i < n_in; i++) {
        long sz = in_sizes[i];
        if (sz == 2L * NE)           { E = (const int*)d_in[i]; nE_total = sz / 2; }
        else if (sz == (long)NN * DIN) X  = (const float*)d_in[i];
        else if (sz == DIN * DH)       W1 = (const float*)d_in[i];
        else if (sz == DH * DH)        W2 = (const float*)d_in[i];
        else if (sz == DH)             { if (!b1) b1 = (const float*)d_in[i];
                                         else     b2 = (const float*)d_in[i]; }
    }
    const int n  = NN;
    const int nE = (int)nE_total;
    const int* src = E;          // E[0]
    const int* dst = E + nE;     // E[1]
    float* out = (float*)d_out;

    void *pXh = nullptr, *pW1h = nullptr, *pXlh = nullptr;
    cudaGetSymbolAddress(&pXh,  g_Xh);
    cudaGetSymbolAddress(&pW1h, g_W1h);
    cudaGetSymbolAddress(&pXlh, g_Xl_h);

    static cudaStream_t s1 = nullptr;
    static cudaEvent_t  eFork = nullptr, eJoin = nullptr;
    if (s1 == nullptr) {
        cudaStreamCreateWithFlags(&s1, cudaStreamNonBlocking);
        cudaEventCreateWithFlags(&eFork, cudaEventDisableTiming);
        cudaEventCreateWithFlags(&eJoin, cudaEventDisableTiming);
    }

    const int T = 256;
    dim3 blkNode((n + T - 1) / T);
    dim3 blkEdge((nE + T - 1) / T);
    dim3 blkGemm((n + 127) / 128);
    dim3 blkWarp(((long)n * 32 + T - 1) / T);
    long nX4 = (long)n * DIN / 4;
    long nConv = nX4 + DIN * DH;
    dim3 blkConv((nConv + T - 1) / T);

    // ---- fork: CSR build (+dinv) on s1, concurrent with conv + GEMM1 ----
    cudaEventRecord(eFork, 0);
    cudaStreamWaitEvent(s1, eFork, 0);

    k_zero_cnt<<<blkNode, T, 0, s1>>>(n);
    k_hist<<<blkEdge, T, 0, s1>>>(dst, nE);
    k_scan1<<<NB_SCAN, 1024, 0, s1>>>(n);
    k_scan23<<<blkNode, T, 0, s1>>>(n);
    k_scatter<<<blkEdge, T, 0, s1>>>(src, dst, nE);
    cudaEventRecord(eJoin, s1);

    // ---- main chain ----
    k_conv<<<blkConv, T>>>(X, W1, W2, nX4);
    k_gemm_tc<DIN><<<blkGemm, T>>>((const __half*)pXh, (const __half*)pW1h,
                                   (__half*)pXlh, n);
    cudaStreamWaitEvent(0, eJoin, 0);

    k_gather_fused<<<blkWarp, T>>>(b1);        // gather1 + relu + H@W2 -> Xl2
    k_gather_out<<<blkWarp, T>>>(b2, out, n);  // gather2 + bias -> output
}

// round 16
// speedup vs baseline: 1.1760x; 1.1760x over previous
#include <cuda_runtime.h>
#include <cuda_fp16.h>
#include <mma.h>
#include <cstdint>

using namespace nvcuda;

// Problem constants (fixed shapes per reference)
#define NN 100000
#define NE 1600000
#define DIN 128
#define DH 64
#define NB_SCAN ((NN + 1023) / 1024)   // 98

// ---------------- scratch (no allocations allowed) ----------------
__device__ float  g_dinv[NN];
__device__ int    g_cnt[NN];
__device__ int    g_rowptr[NN];
__device__ int    g_cursor[NN];
__device__ int    g_bsum[NB_SCAN];
__device__ int    g_csr_src[NE];
__device__ __half g_Xh [NN * DIN];     // X converted to fp16
__device__ __half g_W1h[DIN * DH];
__device__ __half g_W2h[DH * DH];
__device__ __half g_Xl_h[NN * DH];     // transformed features (gather source, fp16)
__device__ __half g_H_h [NN * DH];     // layer-1 activations (fp16)

// ---------------- CSR build ----------------
// int4-vectorized histogram: 4 edges per thread, full grid for latency hiding
__global__ void k_hist4(const int* __restrict__ dst, int nE4) {
    int i = blockIdx.x * blockDim.x + threadIdx.x;
    if (i >= nE4) return;
    int4 d = reinterpret_cast<const int4*>(dst)[i];
    atomicAdd(&g_cnt[d.x], 1);
    atomicAdd(&g_cnt[d.y], 1);
    atomicAdd(&g_cnt[d.z], 1);
    atomicAdd(&g_cnt[d.w], 1);
}

__global__ __launch_bounds__(1024) void k_scan1(int n) {
    __shared__ int s[1024];
    int i = blockIdx.x * 1024 + threadIdx.x;
    int v = (i < n) ? g_cnt[i] : 0;
    s[threadIdx.x] = v;
    __syncthreads();
    for (int off = 1; off < 1024; off <<= 1) {
        int t = (threadIdx.x >= off) ? s[threadIdx.x - off] : 0;
        __syncthreads();
        s[threadIdx.x] += t;
        __syncthreads();
    }
    if (i < n) g_rowptr[i] = s[threadIdx.x] - v;       // exclusive (block-local)
    if (threadIdx.x == 1023) g_bsum[blockIdx.x] = s[1023];
}

// merged scan2+scan3: finalize rowptr, init cursor, compute dinv.
// Warp 0 of each 256-block sums bsum[0..bid/4) directly (<=97 adds).
__global__ __launch_bounds__(256) void k_scan23(int n) {
    __shared__ int sP;
    const int q = blockIdx.x >> 2;
    if (threadIdx.x < 32) {
        int v = 0;
        for (int j = threadIdx.x; j < q; j += 32) v += g_bsum[j];
#pragma unroll
        for (int o = 16; o > 0; o >>= 1) v += __shfl_down_sync(0xffffffffu, v, o);
        if (threadIdx.x == 0) sP = v;
    }
    __syncthreads();
    int i = blockIdx.x * 256 + threadIdx.x;
    if (i >= n) return;
    int rp = g_rowptr[i] + sP;
    g_rowptr[i] = rp;
    g_cursor[i] = rp;
    g_dinv[i] = rsqrtf((float)g_cnt[i] + 1.0f);
}

__global__ void k_scatter(const int* __restrict__ src, const int* __restrict__ dst, int nE) {
    int e = blockIdx.x * blockDim.x + threadIdx.x;
    if (e >= nE) return;
    int d = dst[e];
    int pos = atomicAdd(&g_cursor[d], 1);
    g_csr_src[pos] = src[e];
}

// ---------------- conversions (X + W1 + W2, one kernel) ----------------
__global__ void k_conv(const float* __restrict__ X, const float* __restrict__ W1,
                       const float* __restrict__ W2, long nX4) {
    long i = (long)blockIdx.x * blockDim.x + threadIdx.x;
    if (i < nX4) {
        float4 v = reinterpret_cast<const float4*>(X)[i];
        __half2 h[2];
        h[0] = __floats2half2_rn(v.x, v.y);
        h[1] = __floats2half2_rn(v.z, v.w);
        reinterpret_cast<uint2*>(g_Xh)[i] = *reinterpret_cast<uint2*>(h);
    } else {
        long j = i - nX4;
        if (j < DIN * DH) g_W1h[j] = __float2half_rn(W1[j]);
        if (j < DH * DH)  g_W2h[j] = __float2half_rn(W2[j]);
    }
}

// ---------------- tensor-core GEMM: out = fp16( Xh @ Wh ), fp32 accum ----------------
// Block: 128 rows x 64 cols, 256 threads = 8 warps. Warp w owns rows [16w,16w+16),
// 4 col-tiles of 16. K processed in KT=64 chunks held in padded smem.
template <int K>
__global__ __launch_bounds__(256) void k_gemm_tc(const __half* __restrict__ Xh,
                                                 const __half* __restrict__ Wh,
                                                 __half* __restrict__ outh, int n) {
    constexpr int KT = 64;
    constexpr int NT = K / KT;
    __shared__ __half sA[128][72];          // pad 8 -> conflict-free
    __shared__ __half sB[64][72];
    __shared__ float  sStage[8][16 * 20];

    const int tid = threadIdx.x;
    const int wid = tid >> 5;
    const int lane = tid & 31;
    const int node0 = blockIdx.x * 128;

    const int ar = tid >> 1;          // 0..127
    const int as = (tid & 1) * 32;    // half-offset in KT
    const int br = tid >> 2;          // 0..63
    const int bs = (tid & 3) * 16;

    wmma::fragment<wmma::accumulator, 16, 16, 16, float> facc[4];
#pragma unroll
    for (int c = 0; c < 4; c++) wmma::fill_fragment(facc[c], 0.0f);

    for (int kt = 0; kt < NT; kt++) {
        // load A tile: 128 rows x 64 halves (each thread: 32 halves = 4x uint4)
        {
            const int node = node0 + ar;
            if (node < n) {
                const uint4* srcp = reinterpret_cast<const uint4*>(
                    Xh + (size_t)node * K + kt * KT + as);
                uint4* dstp = reinterpret_cast<uint4*>(&sA[ar][as]);
#pragma unroll
                for (int u = 0; u < 4; u++) dstp[u] = srcp[u];
            } else {
                uint4 z = make_uint4(0, 0, 0, 0);
                uint4* dstp = reinterpret_cast<uint4*>(&sA[ar][as]);
#pragma unroll
                for (int u = 0; u < 4; u++) dstp[u] = z;
            }
        }
        // load B tile: 64 rows x 64 halves (each thread: 16 halves = 2x uint4)
        {
            const uint4* srcp = reinterpret_cast<const uint4*>(
                Wh + (size_t)(kt * KT + br) * DH + bs);
            uint4* dstp = reinterpret_cast<uint4*>(&sB[br][bs]);
            dstp[0] = srcp[0];
            dstp[1] = srcp[1];
        }
        __syncthreads();

#pragma unroll
        for (int k8 = 0; k8 < KT / 16; k8++) {
            wmma::fragment<wmma::matrix_a, 16, 16, 16, __half, wmma::row_major> fa;
            wmma::load_matrix_sync(fa, &sA[wid * 16][k8 * 16], 72);
#pragma unroll
            for (int c = 0; c < 4; c++) {
                wmma::fragment<wmma::matrix_b, 16, 16, 16, __half, wmma::row_major> fb;
                wmma::load_matrix_sync(fb, &sB[k8 * 16][c * 16], 72);
                wmma::mma_sync(facc[c], fa, fb, facc[c]);
            }
        }
        if (kt + 1 < NT) __syncthreads();
    }

    // epilogue: stage fp32 per warp, convert to fp16, store 16B per lane
    const int erow = lane >> 1;          // 0..15
    const int eseg = (lane & 1) * 8;     // 0 or 8
#pragma unroll
    for (int c = 0; c < 4; c++) {
        wmma::store_matrix_sync(&sStage[wid][0], facc[c], 20, wmma::mem_row_major);
        __syncwarp();
        const int node = node0 + wid * 16 + erow;
        if (node < n) {
            const float* sp = &sStage[wid][erow * 20 + eseg];
            __half2 h[4];
            h[0] = __floats2half2_rn(sp[0], sp[1]);
            h[1] = __floats2half2_rn(sp[2], sp[3]);
            h[2] = __floats2half2_rn(sp[4], sp[5]);
            h[3] = __floats2half2_rn(sp[6], sp[7]);
            *reinterpret_cast<uint4*>(outh + (size_t)node * DH + c * 16 + eseg) =
                *reinterpret_cast<uint4*>(h);
        }
        __syncwarp();
    }
}

// ---------------- CSR gather aggregation (fp16 source, fp32 accumulate) ----------------
// One warp per node; lane owns 2 columns (one half2 load per row).
//   acc = dinv[node]*Xl[node] + sum_{s in row} dinv[s]*Xl[s]
//   MODE 0: g_H_h[node] = fp16(relu(acc * dinv + b))
//   MODE 1: out[node]   = acc * dinv + b            (fp32)
template <int MODE>
__global__ __launch_bounds__(256) void k_gather(const float* __restrict__ bias,
                                                float* __restrict__ outbuf, int n) {
    int gw = (blockIdx.x * blockDim.x + threadIdx.x) >> 5;
    if (gw >= n) return;
    const int lane = threadIdx.x & 31;
    const int start = g_rowptr[gw];
    const int cnt   = g_cnt[gw];
    const float dvd = g_dinv[gw];
    const __half2* base = reinterpret_cast<const __half2*>(g_Xl_h);

    float2 acc;
    {
        float2 sf = __half22float2(base[(size_t)gw * 32 + lane]);
        acc.x = sf.x * dvd;
        acc.y = sf.y * dvd;
    }

    int j0 = 0;
    for (; j0 + 32 <= cnt; j0 += 32) {
        int   myidx = g_csr_src[start + j0 + lane];
        float myd   = g_dinv[myidx];
#pragma unroll
        for (int t = 0; t < 32; t++) {
            int   s = __shfl_sync(0xffffffffu, myidx, t);
            float d = __shfl_sync(0xffffffffu, myd,   t);
            float2 v = __half22float2(base[(size_t)s * 32 + lane]);
            acc.x = fmaf(d, v.x, acc.x);
            acc.y = fmaf(d, v.y, acc.y);
        }
    }
    int rem = cnt - j0;
    if (rem > 0) {
        int   myidx = 0; float myd = 0.f;
        if (lane < rem) {
            myidx = g_csr_src[start + j0 + lane];
            myd   = g_dinv[myidx];
        }
        for (int t = 0; t < rem; t++) {
            int   s = __shfl_sync(0xffffffffu, myidx, t);
            float d = __shfl_sync(0xffffffffu, myd,   t);
            float2 v = __half22float2(base[(size_t)s * 32 + lane]);
            acc.x = fmaf(d, v.x, acc.x);
            acc.y = fmaf(d, v.y, acc.y);
        }
    }

    float2 bb = *reinterpret_cast<const float2*>(bias + lane * 2);
    float2 o;
    o.x = fmaf(acc.x, dvd, bb.x);
    o.y = fmaf(acc.y, dvd, bb.y);
    if (MODE == 0) {
        o.x = fmaxf(o.x, 0.f); o.y = fmaxf(o.y, 0.f);
        reinterpret_cast<__half2*>(g_H_h)[(size_t)gw * 32 + lane] =
            __floats2half2_rn(o.x, o.y);
    } else {
        *reinterpret_cast<float2*>(outbuf + (size_t)gw * DH + lane * 2) = o;
    }
}

// ---------------- host launch ----------------
extern "C" void kernel_launch(void* const* d_in, const int* in_sizes, int n_in,
                              void* d_out, int out_size) {
    const int*   E  = nullptr;
    const float* X  = nullptr;
    const float* W1 = nullptr;
    const float* b1 = nullptr;
    const float* W2 = nullptr;
    const float* b2 = nullptr;
    long nE_total = 0;
    for (int i = 0; i < n_in; i++) {
        long sz = in_sizes[i];
        if (sz == 2L * NE)           { E = (const int*)d_in[i]; nE_total = sz / 2; }
        else if (sz == (long)NN * DIN) X  = (const float*)d_in[i];
        else if (sz == DIN * DH)       W1 = (const float*)d_in[i];
        else if (sz == DH * DH)        W2 = (const float*)d_in[i];
        else if (sz == DH)             { if (!b1) b1 = (const float*)d_in[i];
                                         else     b2 = (const float*)d_in[i]; }
    }
    const int n  = NN;
    const int nE = (int)nE_total;
    const int* src = E;          // E[0]
    const int* dst = E + nE;     // E[1]
    float* out = (float*)d_out;

    // device symbol addresses (cannot name device symbols from host as args)
    void *pXh = nullptr, *pW1h = nullptr, *pW2h = nullptr, *pXlh = nullptr,
         *pHh = nullptr, *pCnt = nullptr;
    cudaGetSymbolAddress(&pXh,  g_Xh);
    cudaGetSymbolAddress(&pW1h, g_W1h);
    cudaGetSymbolAddress(&pW2h, g_W2h);
    cudaGetSymbolAddress(&pXlh, g_Xl_h);
    cudaGetSymbolAddress(&pHh,  g_H_h);
    cudaGetSymbolAddress(&pCnt, g_cnt);

    static cudaStream_t s1 = nullptr;
    static cudaEvent_t  eFork = nullptr, eJoin = nullptr;
    if (s1 == nullptr) {
        cudaStreamCreateWithFlags(&s1, cudaStreamNonBlocking);
        cudaEventCreateWithFlags(&eFork, cudaEventDisableTiming);
        cudaEventCreateWithFlags(&eJoin, cudaEventDisableTiming);
    }

    const int T = 256;
    dim3 blkNode((n + T - 1) / T);
    dim3 blkEdge((nE + T - 1) / T);
    dim3 blkEdge4((nE / 4 + T - 1) / T);
    dim3 blkGemm((n + 127) / 128);
    dim3 blkWarp(((long)n * 32 + T - 1) / T);
    long nX4 = (long)n * DIN / 4;
    long nConv = nX4 + DIN * DH;          // X (vec4) + W1 (W2 fits within)
    dim3 blkConv((nConv + T - 1) / T);

    // ---- fork: CSR build (+dinv) on s1, concurrent with conversions + GEMM1 ----
    cudaEventRecord(eFork, 0);
    cudaStreamWaitEvent(s1, eFork, 0);

    cudaMemsetAsync(pCnt, 0, (size_t)n * sizeof(int), s1);
    k_hist4<<<blkEdge4, T, 0, s1>>>(dst, nE / 4);
    k_scan1<<<NB_SCAN, 1024, 0, s1>>>(n);
    k_scan23<<<blkNode, T, 0, s1>>>(n);
    k_scatter<<<blkEdge, T, 0, s1>>>(src, dst, nE);
    cudaEventRecord(eJoin, s1);

    // ---- main chain ----
    k_conv<<<blkConv, T>>>(X, W1, W2, nX4);
    k_gemm_tc<DIN><<<blkGemm, T>>>((const __half*)pXh, (const __half*)pW1h,
                                   (__half*)pXlh, n);
    cudaStreamWaitEvent(0, eJoin, 0);

    k_gather<0><<<blkWarp, T>>>(b1, nullptr, n);
    k_gemm_tc<DH><<<blkGemm, T>>>((const __half*)pHh, (const __half*)pW2h,
                                  (__half*)pXlh, n);
    k_gather<1><<<blkWarp, T>>>(b2, out, n);
}

// round 17
// speedup vs baseline: 1.2154x; 1.0335x over previous
#include <cuda_runtime.h>
#include <cuda_fp16.h>
#include <mma.h>
#include <cstdint>

using namespace nvcuda;

// Problem constants (fixed shapes per reference)
#define NN 100000
#define NE 1600000
#define DIN 128
#define DH 64
#define NB_SCAN ((NN + 1023) / 1024)   // 98

// ---------------- scratch (no allocations allowed) ----------------
__device__ float  g_dinv[NN];
__device__ int    g_cnt[NN];
__device__ int    g_rowptr[NN];
__device__ int    g_cursor[NN];
__device__ int    g_bsum[NB_SCAN];
__device__ int    g_csr_src[NE];
__device__ __half g_Xh [NN * DIN];     // X converted to fp16
__device__ __half g_W1h[DIN * DH];
__device__ __half g_W2h[DH * DH];
__device__ __half g_Xl_h[NN * DH];     // transformed features (L1: raw; L2: pre-scaled)
__device__ __half g_Hs_h[NN * DH];     // dinv-scaled layer-1 activations

// ---------------- CSR build ----------------
// int4-vectorized histogram: 4 edges per thread, full grid for latency hiding
__global__ void k_hist4(const int* __restrict__ dst, int nE4) {
    int i = blockIdx.x * blockDim.x + threadIdx.x;
    if (i >= nE4) return;
    int4 d = reinterpret_cast<const int4*>(dst)[i];
    atomicAdd(&g_cnt[d.x], 1);
    atomicAdd(&g_cnt[d.y], 1);
    atomicAdd(&g_cnt[d.z], 1);
    atomicAdd(&g_cnt[d.w], 1);
}

__global__ __launch_bounds__(1024) void k_scan1(int n) {
    __shared__ int s[1024];
    int i = blockIdx.x * 1024 + threadIdx.x;
    int v = (i < n) ? g_cnt[i] : 0;
    s[threadIdx.x] = v;
    __syncthreads();
    for (int off = 1; off < 1024; off <<= 1) {
        int t = (threadIdx.x >= off) ? s[threadIdx.x - off] : 0;
        __syncthreads();
        s[threadIdx.x] += t;
        __syncthreads();
    }
    if (i < n) g_rowptr[i] = s[threadIdx.x] - v;       // exclusive (block-local)
    if (threadIdx.x == 1023) g_bsum[blockIdx.x] = s[1023];
}

// merged scan2+scan3: finalize rowptr, init cursor, compute dinv.
// Warp 0 of each 256-block sums bsum[0..bid/4) directly (<=97 adds).
__global__ __launch_bounds__(256) void k_scan23(int n) {
    __shared__ int sP;
    const int q = blockIdx.x >> 2;
    if (threadIdx.x < 32) {
        int v = 0;
        for (int j = threadIdx.x; j < q; j += 32) v += g_bsum[j];
#pragma unroll
        for (int o = 16; o > 0; o >>= 1) v += __shfl_down_sync(0xffffffffu, v, o);
        if (threadIdx.x == 0) sP = v;
    }
    __syncthreads();
    int i = blockIdx.x * 256 + threadIdx.x;
    if (i >= n) return;
    int rp = g_rowptr[i] + sP;
    g_rowptr[i] = rp;
    g_cursor[i] = rp;
    g_dinv[i] = rsqrtf((float)g_cnt[i] + 1.0f);
}

__global__ void k_scatter(const int* __restrict__ src, const int* __restrict__ dst, int nE) {
    int e = blockIdx.x * blockDim.x + threadIdx.x;
    if (e >= nE) return;
    int d = dst[e];
    int pos = atomicAdd(&g_cursor[d], 1);
    g_csr_src[pos] = src[e];
}

// ---------------- conversions (X + W1 + W2, one kernel) ----------------
__global__ void k_conv(const float* __restrict__ X, const float* __restrict__ W1,
                       const float* __restrict__ W2, long nX4) {
    long i = (long)blockIdx.x * blockDim.x + threadIdx.x;
    if (i < nX4) {
        float4 v = reinterpret_cast<const float4*>(X)[i];
        __half2 h[2];
        h[0] = __floats2half2_rn(v.x, v.y);
        h[1] = __floats2half2_rn(v.z, v.w);
        reinterpret_cast<uint2*>(g_Xh)[i] = *reinterpret_cast<uint2*>(h);
    } else {
        long j = i - nX4;
        if (j < DIN * DH) g_W1h[j] = __float2half_rn(W1[j]);
        if (j < DH * DH)  g_W2h[j] = __float2half_rn(W2[j]);
    }
}

// ---------------- tensor-core GEMM: out = fp16( Xh @ Wh ), fp32 accum ----------------
template <int K>
__global__ __launch_bounds__(256) void k_gemm_tc(const __half* __restrict__ Xh,
                                                 const __half* __restrict__ Wh,
                                                 __half* __restrict__ outh, int n) {
    constexpr int KT = 64;
    constexpr int NT = K / KT;
    __shared__ __half sA[128][72];          // pad 8 -> conflict-free
    __shared__ __half sB[64][72];
    __shared__ float  sStage[8][16 * 20];

    const int tid = threadIdx.x;
    const int wid = tid >> 5;
    const int lane = tid & 31;
    const int node0 = blockIdx.x * 128;

    const int ar = tid >> 1;          // 0..127
    const int as = (tid & 1) * 32;    // half-offset in KT
    const int br = tid >> 2;          // 0..63
    const int bs = (tid & 3) * 16;

    wmma::fragment<wmma::accumulator, 16, 16, 16, float> facc[4];
#pragma unroll
    for (int c = 0; c < 4; c++) wmma::fill_fragment(facc[c], 0.0f);

    for (int kt = 0; kt < NT; kt++) {
        {
            const int node = node0 + ar;
            if (node < n) {
                const uint4* srcp = reinterpret_cast<const uint4*>(
                    Xh + (size_t)node * K + kt * KT + as);
                uint4* dstp = reinterpret_cast<uint4*>(&sA[ar][as]);
#pragma unroll
                for (int u = 0; u < 4; u++) dstp[u] = srcp[u];
            } else {
                uint4 z = make_uint4(0, 0, 0, 0);
                uint4* dstp = reinterpret_cast<uint4*>(&sA[ar][as]);
#pragma unroll
                for (int u = 0; u < 4; u++) dstp[u] = z;
            }
        }
        {
            const uint4* srcp = reinterpret_cast<const uint4*>(
                Wh + (size_t)(kt * KT + br) * DH + bs);
            uint4* dstp = reinterpret_cast<uint4*>(&sB[br][bs]);
            dstp[0] = srcp[0];
            dstp[1] = srcp[1];
        }
        __syncthreads();

#pragma unroll
        for (int k8 = 0; k8 < KT / 16; k8++) {
            wmma::fragment<wmma::matrix_a, 16, 16, 16, __half, wmma::row_major> fa;
            wmma::load_matrix_sync(fa, &sA[wid * 16][k8 * 16], 72);
#pragma unroll
            for (int c = 0; c < 4; c++) {
                wmma::fragment<wmma::matrix_b, 16, 16, 16, __half, wmma::row_major> fb;
                wmma::load_matrix_sync(fb, &sB[k8 * 16][c * 16], 72);
                wmma::mma_sync(facc[c], fa, fb, facc[c]);
            }
        }
        if (kt + 1 < NT) __syncthreads();
    }

    const int erow = lane >> 1;          // 0..15
    const int eseg = (lane & 1) * 8;     // 0 or 8
#pragma unroll
    for (int c = 0; c < 4; c++) {
        wmma::store_matrix_sync(&sStage[wid][0], facc[c], 20, wmma::mem_row_major);
        __syncwarp();
        const int node = node0 + wid * 16 + erow;
        if (node < n) {
            const float* sp = &sStage[wid][erow * 20 + eseg];
            __half2 h[4];
            h[0] = __floats2half2_rn(sp[0], sp[1]);
            h[1] = __floats2half2_rn(sp[2], sp[3]);
            h[2] = __floats2half2_rn(sp[4], sp[5]);
            h[3] = __floats2half2_rn(sp[6], sp[7]);
            *reinterpret_cast<uint4*>(outh + (size_t)node * DH + c * 16 + eseg) =
                *reinterpret_cast<uint4*>(h);
        }
        __syncwarp();
    }
}

// ---------------- CSR gather aggregation (fp16 source, fp32 accumulate) ----------------
// One warp per node; lane owns 2 columns (one half2 load per row).
// PDINV=1 (layer 1): rows RAW, weight each by dinv[src]:
//   acc = dinv_self*Xl[gw] + sum dinv_s*Xl[s]
//   Hs[gw] = fp16( dinv * relu(acc*dinv + b1) )      <- pre-scaled for layer 2
// PDINV=0 (layer 2): rows already pre-scaled by dinv[src]:
//   acc = Xl[gw] + sum Xl[s];  out[gw] = acc*dinv + b2  (fp32)
template <int MODE, int PDINV>
__global__ __launch_bounds__(256) void k_gather(const float* __restrict__ bias,
                                                float* __restrict__ outbuf, int n) {
    int gw = (blockIdx.x * blockDim.x + threadIdx.x) >> 5;
    if (gw >= n) return;
    const int lane = threadIdx.x & 31;
    const int start = g_rowptr[gw];
    const int cnt   = g_cnt[gw];
    const float dvd = g_dinv[gw];
    const __half2* base = reinterpret_cast<const __half2*>(g_Xl_h);

    float2 acc;
    {
        float2 sf = __half22float2(base[(size_t)gw * 32 + lane]);
        const float w = PDINV ? dvd : 1.0f;
        acc.x = sf.x * w;
        acc.y = sf.y * w;
    }

    int j0 = 0;
    for (; j0 + 32 <= cnt; j0 += 32) {
        int   myidx = g_csr_src[start + j0 + lane];
        float myd   = PDINV ? g_dinv[myidx] : 0.f;
#pragma unroll
        for (int t = 0; t < 32; t++) {
            int s = __shfl_sync(0xffffffffu, myidx, t);
            float2 v = __half22float2(base[(size_t)s * 32 + lane]);
            if (PDINV) {
                float d = __shfl_sync(0xffffffffu, myd, t);
                acc.x = fmaf(d, v.x, acc.x);
                acc.y = fmaf(d, v.y, acc.y);
            } else {
                acc.x += v.x; acc.y += v.y;
            }
        }
    }
    int rem = cnt - j0;
    if (rem > 0) {
        int   myidx = 0; float myd = 0.f;
        if (lane < rem) {
            myidx = g_csr_src[start + j0 + lane];
            if (PDINV) myd = g_dinv[myidx];
        }
        for (int t = 0; t < rem; t++) {
            int s = __shfl_sync(0xffffffffu, myidx, t);
            float2 v = __half22float2(base[(size_t)s * 32 + lane]);
            if (PDINV) {
                float d = __shfl_sync(0xffffffffu, myd, t);
                acc.x = fmaf(d, v.x, acc.x);
                acc.y = fmaf(d, v.y, acc.y);
            } else {
                acc.x += v.x; acc.y += v.y;
            }
        }
    }

    float2 bb = *reinterpret_cast<const float2*>(bias + lane * 2);
    float2 o;
    o.x = fmaf(acc.x, dvd, bb.x);
    o.y = fmaf(acc.y, dvd, bb.y);
    if (MODE == 0) {
        o.x = fmaxf(o.x, 0.f) * dvd;        // pre-scale H for layer 2
        o.y = fmaxf(o.y, 0.f) * dvd;
        reinterpret_cast<__half2*>(g_Hs_h)[(size_t)gw * 32 + lane] =
            __floats2half2_rn(o.x, o.y);
    } else {
        *reinterpret_cast<float2*>(outbuf + (size_t)gw * DH + lane * 2) = o;
    }
}

// ---------------- host launch ----------------
extern "C" void kernel_launch(void* const* d_in, const int* in_sizes, int n_in,
                              void* d_out, int out_size) {
    const int*   E  = nullptr;
    const float* X  = nullptr;
    const float* W1 = nullptr;
    const float* b1 = nullptr;
    const float* W2 = nullptr;
    const float* b2 = nullptr;
    long nE_total = 0;
    for (int i = 0; i < n_in; i++) {
        long sz = in_sizes[i];
        if (sz == 2L * NE)           { E = (const int*)d_in[i]; nE_total = sz / 2; }
        else if (sz == (long)NN * DIN) X  = (const float*)d_in[i];
        else if (sz == DIN * DH)       W1 = (const float*)d_in[i];
        else if (sz == DH * DH)        W2 = (const float*)d_in[i];
        else if (sz == DH)             { if (!b1) b1 = (const float*)d_in[i];
                                         else     b2 = (const float*)d_in[i]; }
    }
    const int n  = NN;
    const int nE = (int)nE_total;
    const int* src = E;          // E[0]
    const int* dst = E + nE;     // E[1]
    float* out = (float*)d_out;

    void *pXh = nullptr, *pW1h = nullptr, *pW2h = nullptr, *pXlh = nullptr,
         *pHsh = nullptr, *pCnt = nullptr;
    cudaGetSymbolAddress(&pXh,  g_Xh);
    cudaGetSymbolAddress(&pW1h, g_W1h);
    cudaGetSymbolAddress(&pW2h, g_W2h);
    cudaGetSymbolAddress(&pXlh, g_Xl_h);
    cudaGetSymbolAddress(&pHsh, g_Hs_h);
    cudaGetSymbolAddress(&pCnt, g_cnt);

    static cudaStream_t s1 = nullptr;
    static cudaEvent_t  eFork = nullptr, eJoin = nullptr;
    if (s1 == nullptr) {
        cudaStreamCreateWithFlags(&s1, cudaStreamNonBlocking);
        cudaEventCreateWithFlags(&eFork, cudaEventDisableTiming);
        cudaEventCreateWithFlags(&eJoin, cudaEventDisableTiming);
    }

    const int T = 256;
    dim3 blkNode((n + T - 1) / T);
    dim3 blkEdge((nE + T - 1) / T);
    dim3 blkEdge4((nE / 4 + T - 1) / T);
    dim3 blkGemm((n + 127) / 128);
    dim3 blkWarp(((long)n * 32 + T - 1) / T);
    long nX4 = (long)n * DIN / 4;
    long nConv = nX4 + DIN * DH;
    dim3 blkConv((nConv + T - 1) / T);

    // ---- fork: CSR build (+dinv) on s1, concurrent with conversions + GEMM1 ----
    cudaEventRecord(eFork, 0);
    cudaStreamWaitEvent(s1, eFork, 0);

    cudaMemsetAsync(pCnt, 0, (size_t)n * sizeof(int), s1);
    k_hist4<<<blkEdge4, T, 0, s1>>>(dst, nE / 4);
    k_scan1<<<NB_SCAN, 1024, 0, s1>>>(n);
    k_scan23<<<blkNode, T, 0, s1>>>(n);
    k_scatter<<<blkEdge, T, 0, s1>>>(src, dst, nE);
    cudaEventRecord(eJoin, s1);

    // ---- main chain ----
    k_conv<<<blkConv, T>>>(X, W1, W2, nX4);
    k_gemm_tc<DIN><<<blkGemm, T>>>((const __half*)pXh, (const __half*)pW1h,
                                   (__half*)pXlh, n);
    cudaStreamWaitEvent(0, eJoin, 0);

    k_gather<0, 1><<<blkWarp, T>>>(b1, nullptr, n);    // per-edge dinv -> Hs (pre-scaled)
    k_gemm_tc<DH><<<blkGemm, T>>>((const __half*)pHsh, (const __half*)pW2h,
                                  (__half*)pXlh, n);   // Xl2 inherits pre-scale
    k_gather<1, 0><<<blkWarp, T>>>(b2, out, n);        // plain-sum gather
}